// round 2
// baseline (speedup 1.0000x reference)
#include <cuda_runtime.h>
#include <math.h>

// ROI max pooling (Fast R-CNN convention), matching the JAX reference:
//   x:    (B=4, C=256, H=50, W=50) float32
//   rois: (M, 5) float32  [batch_idx, x1, y1, x2, y2] in image coords
//   out:  (M, C, 7, 7) float32
//
// KEY numeric detail: XLA rewrites `roi_h / 7` into `roi_h * RN(1/7)`.
// We must do the same multiply-by-reciprocal to match bin boundaries exactly
// (division gives a different 1-ulp result for e.g. roi_h = 21, which shifts
// floor/ceil bin edges).

#define POOL_H 7
#define POOL_W 7

static constexpr int   kC = 256;
static constexpr int   kH = 50;
static constexpr int   kW = 50;
static constexpr float kScale = 0.0625f;

__global__ void roi_pool_kernel(const float* __restrict__ x,
                                const float* __restrict__ rois,
                                float* __restrict__ out,
                                int M)
{
    int tid = blockIdx.x * blockDim.x + threadIdx.x;
    int total = M * kC * POOL_H * POOL_W;
    if (tid >= total) return;

    int pw = tid % POOL_W;
    int ph = (tid / POOL_W) % POOL_H;
    int c  = (tid / (POOL_W * POOL_H)) % kC;
    int m  = tid / (POOL_W * POOL_H * kC);

    const float* r = rois + (size_t)m * 5;
    int b  = (int)r[0];
    // jnp.round = round half to even -> __float2int_rn (scale by 2^-4 is exact)
    int x1 = __float2int_rn(r[1] * kScale);
    int y1 = __float2int_rn(r[2] * kScale);
    int x2 = __float2int_rn(r[3] * kScale);
    int y2 = __float2int_rn(r[4] * kScale);

    float roi_h = (float)max(y2 - y1 + 1, 1);
    float roi_w = (float)max(x2 - x1 + 1, 1);

    // Match XLA: division by constant becomes multiply by RN(1/7).
    const float kInv7 = 1.0f / 7.0f;   // constant-folded, RN = 0x3E124925
    float bin_h = roi_h * kInv7;
    float bin_w = roi_w * kInv7;

    int hs = min(max((int)floorf((float)ph * bin_h) + y1, 0), kH);
    int he = min(max((int)ceilf((float)(ph + 1) * bin_h) + y1, 0), kH);
    int ws = min(max((int)floorf((float)pw * bin_w) + x1, 0), kW);
    int we = min(max((int)ceilf((float)(pw + 1) * bin_w) + x1, 0), kW);

    const float* feat = x + ((size_t)b * kC + c) * (kH * kW);

    float v = -INFINITY;
    for (int h = hs; h < he; ++h) {
        const float* row = feat + h * kW;
        for (int w = ws; w < we; ++w) {
            v = fmaxf(v, __ldg(row + w));
        }
    }
    bool empty = (he <= hs) || (we <= ws);
    out[tid] = empty ? 0.0f : v;
}

extern "C" void kernel_launch(void* const* d_in, const int* in_sizes, int n_in,
                              void* d_out, int out_size)
{
    const float* x    = (const float*)d_in[0];
    const float* rois = (const float*)d_in[1];
    float*       out  = (float*)d_out;

    int M = in_sizes[1] / 5;
    int total = M * kC * POOL_H * POOL_W;
    int threads = 256;
    int blocks = (total + threads - 1) / threads;
    roi_pool_kernel<<<blocks, threads>>>(x, rois, out, M);
}